// round 8
// baseline (speedup 1.0000x reference)
#include <cuda_runtime.h>

#define SO 160                 // fine grid size
#define SV (SO*SO*SO)
#define DC 96                  // coarse grid size
#define IMH 240
#define IMW 320
#define NVIEW 3
#define NPIX (NVIEW*IMH*IMW)

// ---- device-global scratch (no cudaMalloc allowed) ----
__device__ float4 g4[SV];                    // packed yz-quad fine SDF, 64 MB
__device__ float  g_t[NPIX];                 // final ray parameter per pixel
__device__ double g_sum;                     // loss numerator
__device__ unsigned int g_cnt;               // count of valid pixels

__constant__ float c_off[3][3] = {{0.f,0.f,0.f},{36.f,0.f,44.f},{40.f,0.f,23.f}};

// ------------------------------------------------------------------
// Trilerp pair from the coarse grid: returns fine value v at (x,y,z) and
// vy at (x, y+1, z), sharing the 2x3x2 coarse patch.
__device__ __forceinline__ void trilerp_pair(const float* __restrict__ src,
                                             int gx0, int gx1, float fx,
                                             int y0, int y1, int y2,
                                             float fy, float fy2, int dy,
                                             int gz0, int gz1, float fz,
                                             float& v, float& vy) {
    int bx0 = gx0 * DC, bx1 = gx1 * DC;
    int r00 = (bx0 + y0) * DC, r01 = (bx0 + y1) * DC, r02 = (bx0 + y2) * DC;
    int r10 = (bx1 + y0) * DC, r11 = (bx1 + y1) * DC, r12 = (bx1 + y2) * DC;
    float a00 = __ldg(src + r00 + gz0), a01 = __ldg(src + r00 + gz1);
    float a10 = __ldg(src + r01 + gz0), a11 = __ldg(src + r01 + gz1);
    float a20 = __ldg(src + r02 + gz0), a21 = __ldg(src + r02 + gz1);
    float b00 = __ldg(src + r10 + gz0), b01 = __ldg(src + r10 + gz1);
    float b10 = __ldg(src + r11 + gz0), b11 = __ldg(src + r11 + gz1);
    float b20 = __ldg(src + r12 + gz0), b21 = __ldg(src + r12 + gz1);
    // x-lerp
    float p00 = a00 + fx * (b00 - a00), p01 = a01 + fx * (b01 - a01);
    float p10 = a10 + fx * (b10 - a10), p11 = a11 + fx * (b11 - a11);
    float p20 = a20 + fx * (b20 - a20), p21 = a21 + fx * (b21 - a21);
    // z-lerp
    float R0 = p00 + fz * (p01 - p00);
    float R1 = p10 + fz * (p11 - p10);
    float R2 = p20 + fz * (p21 - p20);
    // y-lerp
    v = R0 + fy * (R1 - R0);
    float Ra = dy ? R1 : R0;
    float Rb = dy ? R2 : R1;
    vy = Ra + fy2 * (Rb - Ra);
}

// ------------------------------------------------------------------
// Fused: trilinear upsample 96^3 -> 160^3 (minus TRUNC) AND pack into
// g4[x][y][z] = { v(y,z), v(y,z+1), v(y+1,z), v(y+1,z+1) }.
// Lanes map along z; the z+1 components come from the next lane via shfl.
__global__ void __launch_bounds__(256) k_resize_pack(const float* __restrict__ src) {
    if (blockIdx.x == 0 && blockIdx.y == 0 && blockIdx.z == 0 &&
        threadIdx.x == 0 && threadIdx.y == 0) {
        g_sum = 0.0; g_cnt = 0u;    // fold k_zero in here (runs before shade)
    }
    const float SCL = 95.0f / 159.0f;
    int lane = threadIdx.x;                    // 0..31 -> z within chunk
    int z = blockIdx.x * 32 + lane;
    int y = blockIdx.y * 8 + threadIdx.y;
    int x = blockIdx.z;

    float cx = x * SCL;
    int gx0 = (int)cx; float fx = cx - (float)gx0;
    int gx1 = min(gx0 + 1, DC - 1);

    float cy = y * SCL;
    int gy0 = (int)cy; float fy = cy - (float)gy0;
    int yb = min(y + 1, SO - 1);
    float cy2 = yb * SCL;
    int gy0b = (int)cy2; float fy2 = cy2 - (float)gy0b;
    int dy = gy0b - gy0;                       // 0 or 1
    int y0 = gy0, y1 = min(gy0 + 1, DC - 1), y2 = min(gy0 + 2, DC - 1);

    float cz = z * SCL;
    int gz0 = (int)cz; float fz = cz - (float)gz0;
    int gz1 = min(gz0 + 1, DC - 1);

    float v, vy;
    trilerp_pair(src, gx0, gx1, fx, y0, y1, y2, fy, fy2, dy, gz0, gz1, fz, v, vy);

    // lane 31 computes its own z+1 values (next lane is out of warp)
    float vn = 0.f, vyn = 0.f;
    if (lane == 31) {
        int z2 = min(z + 1, SO - 1);
        float czn = z2 * SCL;
        int gz0n = (int)czn; float fzn = czn - (float)gz0n;
        int gz1n = min(gz0n + 1, DC - 1);
        trilerp_pair(src, gx0, gx1, fx, y0, y1, y2, fy, fy2, dy, gz0n, gz1n, fzn, vn, vyn);
    }
    float vzp  = __shfl_down_sync(0xFFFFFFFFu, v, 1);
    float vyzp = __shfl_down_sync(0xFFFFFFFFu, vy, 1);
    if (lane == 31) { vzp = vn; vyzp = vyn; }

    float4 q;
    q.x = v    - 1.5f;
    q.y = vzp  - 1.5f;
    q.z = vy   - 1.5f;
    q.w = vyzp - 1.5f;
    g4[(x * SO + y) * SO + z] = q;
}

// ------------------------------------------------------------------
// Trilerp of the fine SDF via the packed quads (2x LDG.128).
__device__ __forceinline__ float tl_sdf4(float px, float py, float pz) {
    px = fminf(fmaxf(px, 0.0f), 158.999f);
    py = fminf(fmaxf(py, 0.0f), 158.999f);
    pz = fminf(fmaxf(pz, 0.0f), 158.999f);
    int x0 = (int)px, y0 = (int)py, z0 = (int)pz;
    float fx = px - (float)x0, fy = py - (float)y0, fz = pz - (float)z0;
    int idx = (x0 * SO + y0) * SO + z0;
    float4 A = __ldg(&g4[idx]);
    float4 B = __ldg(&g4[idx + SO * SO]);
    float a0 = A.x + fz * (A.y - A.x);
    float a1 = A.z + fz * (A.w - A.z);
    float ea = a0 + fy * (a1 - a0);
    float b0 = B.x + fz * (B.y - B.x);
    float b1 = B.z + fz * (B.w - B.z);
    float eb = b0 + fy * (b1 - b0);
    return ea + fx * (eb - ea);
}

// Recompute ray (origin, dir) for view v, pixel (h, w)
__device__ __forceinline__ void ray_setup_vhw(const float* __restrict__ poses,
                                              int v, int h, int w,
                                              float& ox, float& oy, float& oz,
                                              float& dx, float& dy, float& dz) {
    const float* M = poses + v * 16;
    float u  = ((float)w - 160.0f) / 277.0f;
    float vv = ((float)h - 120.0f) / 277.0f;
    dx = M[0] * u + M[1] * vv + M[2];
    dy = M[4] * u + M[5] * vv + M[6];
    dz = M[8] * u + M[9] * vv + M[10];
    float inv = rsqrtf(dx * dx + dy * dy + dz * dz);
    dx *= inv; dy *= inv; dz *= inv;
    ox = M[3]  / 0.0301f + c_off[v][0];
    oy = M[7]  / 0.0301f + c_off[v][1];
    oz = M[11] / 0.0301f + c_off[v][2];
}

// ------------------------------------------------------------------
// Sphere trace: 64 dependent steps, TWO independent rays per thread.
__global__ void __launch_bounds__(256) k_march(const float* __restrict__ poses) {
    int tx = threadIdx.x & 15;
    int ty = threadIdx.x >> 4;
    int w0 = blockIdx.x * 32 + tx;
    int w1 = w0 + 16;
    int h = blockIdx.y * 16 + ty;
    int v = blockIdx.z;

    float ox0, oy0, oz0, dx0, dy0, dz0;
    float ox1, oy1, oz1, dx1, dy1, dz1;
    ray_setup_vhw(poses, v, h, w0, ox0, oy0, oz0, dx0, dy0, dz0);
    ray_setup_vhw(poses, v, h, w1, ox1, oy1, oz1, dx1, dy1, dz1);

    const float    MAG   = 8388608.0f;            // 2^23
    const float    MAGH  = 8388607.5f;            // 2^23 - 0.5
    const unsigned MAGI  = 0x4B000000u;           // bits of 2^23
    const unsigned MAGOF = MAGI * (unsigned)(SO * SO + SO + 1); // fold (wraps)

    float t0 = 0.0f, t1 = 0.0f;
    #pragma unroll 1
    for (int i = 0; i < 64; i++) {
        // ---- ray 0 address ----
        float px0 = ox0 + t0 * dx0, py0 = oy0 + t0 * dy0, pz0 = oz0 + t0 * dz0;
        px0 = fminf(fmaxf(px0, 0.0f), 158.999f);
        py0 = fminf(fmaxf(py0, 0.0f), 158.999f);
        pz0 = fminf(fmaxf(pz0, 0.0f), 158.999f);
        float txm0 = px0 + MAGH, tym0 = py0 + MAGH, tzm0 = pz0 + MAGH;
        float fx0 = px0 - (txm0 - MAG);
        float fy0 = py0 - (tym0 - MAG);
        float fz0 = pz0 - (tzm0 - MAG);
        int idx0 = (int)(__float_as_uint(txm0) * (unsigned)(SO * SO)
                       + __float_as_uint(tym0) * (unsigned)SO
                       + __float_as_uint(tzm0) - MAGOF);
        // ---- ray 1 address ----
        float px1 = ox1 + t1 * dx1, py1 = oy1 + t1 * dy1, pz1 = oz1 + t1 * dz1;
        px1 = fminf(fmaxf(px1, 0.0f), 158.999f);
        py1 = fminf(fmaxf(py1, 0.0f), 158.999f);
        pz1 = fminf(fmaxf(pz1, 0.0f), 158.999f);
        float txm1 = px1 + MAGH, tym1 = py1 + MAGH, tzm1 = pz1 + MAGH;
        float fx1 = px1 - (txm1 - MAG);
        float fy1 = py1 - (tym1 - MAG);
        float fz1 = pz1 - (tzm1 - MAG);
        int idx1 = (int)(__float_as_uint(txm1) * (unsigned)(SO * SO)
                       + __float_as_uint(tym1) * (unsigned)SO
                       + __float_as_uint(tzm1) - MAGOF);

        // ---- 4 loads in flight ----
        float4 A0 = __ldg(&g4[idx0]);
        float4 B0 = __ldg(&g4[idx0 + SO * SO]);
        float4 A1 = __ldg(&g4[idx1]);
        float4 B1 = __ldg(&g4[idx1 + SO * SO]);

        // ---- ray 0 lerp + step ----
        float a0 = A0.x + fz0 * (A0.y - A0.x);
        float a1 = A0.z + fz0 * (A0.w - A0.z);
        float ea = a0 + fy0 * (a1 - a0);
        float b0 = B0.x + fz0 * (B0.y - B0.x);
        float b1 = B0.z + fz0 * (B0.w - B0.z);
        float eb = b0 + fy0 * (b1 - b0);
        float s0 = ea + fx0 * (eb - ea);
        t0 += fmaxf(s0, 0.25f) * 2.0f;

        // ---- ray 1 lerp + step ----
        float c0 = A1.x + fz1 * (A1.y - A1.x);
        float c1 = A1.z + fz1 * (A1.w - A1.z);
        float ec = c0 + fy1 * (c1 - c0);
        float d0 = B1.x + fz1 * (B1.y - B1.x);
        float d1 = B1.z + fz1 * (B1.w - B1.z);
        float ed = d0 + fy1 * (d1 - d0);
        float s1 = ec + fx1 * (ed - ec);
        t1 += fmaxf(s1, 0.25f) * 2.0f;
    }
    int base = (v * IMH + h) * IMW;
    g_t[base + w0] = t0;
    g_t[base + w1] = t1;
}

// ------------------------------------------------------------------
// Final shading + masked weighted-L1 reduction.
__global__ void __launch_bounds__(128) k_shade(const float* __restrict__ poses,
                                               const float* __restrict__ rgb,
                                               const float* __restrict__ sem,
                                               const float* __restrict__ views) {
    int idx = blockIdx.x * blockDim.x + threadIdx.x;
    float contrib = 0.0f;
    int cval = 0;

    if (idx < NPIX) {
        int w = idx % IMW;
        int h = (idx / IMW) % IMH;
        int v = idx / (IMW * IMH);
        float ox, oy, oz, dx, dy, dz;
        ray_setup_vhw(poses, v, h, w, ox, oy, oz, dx, dy, dz);
        float t = g_t[idx];
        float px = ox + t * dx;
        float py = oy + t * dy;
        float pz = oz + t * dz;
        float s = tl_sdf4(px, py, pz);
        bool inside = (px >= 0.f) && (px <= 159.f) &&
                      (py >= 0.f) && (py <= 159.f) &&
                      (pz >= 0.f) && (pz <= 159.f);
        if (inside && fabsf(s) < 1.0f) {
            float cpx = fminf(fmaxf(px, 0.0f), 158.999f);
            float cpy = fminf(fmaxf(py, 0.0f), 158.999f);
            float cpz = fminf(fmaxf(pz, 0.0f), 158.999f);
            int X0 = (int)cpx, Y0 = (int)cpy, Z0 = (int)cpz;
            float FXf = cpx - (float)X0, FYf = cpy - (float)Y0, FZf = cpz - (float)Z0;
            int Xc[2] = {X0, min(X0 + 1, SO - 1)};
            int Yc[2] = {Y0, min(Y0 + 1, SO - 1)};
            int Zc[2] = {Z0, min(Z0 + 1, SO - 1)};
            float WX[2] = {1.f - FXf, FXf};
            float WY[2] = {1.f - FYf, FYf};
            float WZ[2] = {1.f - FZf, FZf};

            const float SCL = 95.0f / 159.0f;
            int   GX0[2], GX1[2], SX[2]; float GFX[2];
            int   GY0[2], GY1[2], SY[2]; float GFY[2];
            int   GZ0[2], GZ1[2], SZ[2]; float GFZ[2];
            #pragma unroll
            for (int a = 0; a < 2; a++) {
                float cc;
                cc = (float)Xc[a] * SCL;
                GX0[a] = min((int)cc, DC - 1); GFX[a] = cc - (float)GX0[a]; GX1[a] = min(GX0[a] + 1, DC - 1);
                SX[a] = min((int)((float)Xc[a] * 0.6f), DC - 1);
                cc = (float)Yc[a] * SCL;
                GY0[a] = min((int)cc, DC - 1); GFY[a] = cc - (float)GY0[a]; GY1[a] = min(GY0[a] + 1, DC - 1);
                SY[a] = min((int)((float)Yc[a] * 0.6f), DC - 1);
                cc = (float)Zc[a] * SCL;
                GZ0[a] = min((int)cc, DC - 1); GFZ[a] = cc - (float)GZ0[a]; GZ1[a] = min(GZ0[a] + 1, DC - 1);
                SZ[a] = min((int)((float)Zc[a] * 0.6f), DC - 1);
            }

            float rr = 0.f, gg = 0.f, bb = 0.f, ws = 0.f;
            const int DD = DC * DC * DC;
            #pragma unroll
            for (int a = 0; a < 2; a++) {
                #pragma unroll
                for (int b = 0; b < 2; b++) {
                    #pragma unroll
                    for (int c = 0; c < 2; c++) {
                        float wgt = WX[a] * WY[b] * WZ[c];
                        float fx = GFX[a], fy = GFY[b], fz = GFZ[c];
                        float gx = 1.f - fx, gy = 1.f - fy, gz = 1.f - fz;
                        float w000 = gx*gy*gz, w100 = fx*gy*gz, w010 = gx*fy*gz, w001 = gx*gy*fz;
                        float w110 = fx*fy*gz, w101 = fx*gy*fz, w011 = gx*fy*fz, w111 = fx*fy*fz;
                        int i00 = (GX0[a] * DC + GY0[b]) * DC;
                        int i01 = (GX0[a] * DC + GY1[b]) * DC;
                        int i10 = (GX1[a] * DC + GY0[b]) * DC;
                        int i11 = (GX1[a] * DC + GY1[b]) * DC;
                        int z0 = GZ0[c], z1 = GZ1[c];
                        #pragma unroll
                        for (int ch = 0; ch < 3; ch++) {
                            const float* base = rgb + ch * DD;
                            float val = __ldg(&base[i00 + z0]) * w000
                                      + __ldg(&base[i10 + z0]) * w100
                                      + __ldg(&base[i01 + z0]) * w010
                                      + __ldg(&base[i00 + z1]) * w001
                                      + __ldg(&base[i11 + z0]) * w110
                                      + __ldg(&base[i10 + z1]) * w101
                                      + __ldg(&base[i01 + z1]) * w011
                                      + __ldg(&base[i11 + z1]) * w111;
                            if (ch == 0) rr += wgt * val;
                            else if (ch == 1) gg += wgt * val;
                            else bb += wgt * val;
                        }
                        ws += wgt * __ldg(&sem[(SX[a] * DC + SY[b]) * DC + SZ[c]]);
                    }
                }
            }

            const float* vp = views + ((size_t)(v * IMH + h) * IMW + w) * 3;
            float l = fabsf(rr - vp[0]) + fabsf(gg - vp[1]) + fabsf(bb - vp[2]);
            contrib = ws * l;
            cval = 1;
        }
    }

    // warp reduce
    #pragma unroll
    for (int o = 16; o > 0; o >>= 1) {
        contrib += __shfl_down_sync(0xFFFFFFFFu, contrib, o);
        cval    += __shfl_down_sync(0xFFFFFFFFu, cval, o);
    }
    __shared__ float ssum[4];
    __shared__ int scnt[4];
    int lane = threadIdx.x & 31;
    int wid = threadIdx.x >> 5;
    if (lane == 0) { ssum[wid] = contrib; scnt[wid] = cval; }
    __syncthreads();
    if (wid == 0) {
        float bs = (lane < 4) ? ssum[lane] : 0.f;
        int bc = (lane < 4) ? scnt[lane] : 0;
        #pragma unroll
        for (int o = 2; o > 0; o >>= 1) {
            bs += __shfl_down_sync(0xFFFFFFFFu, bs, o);
            bc += __shfl_down_sync(0xFFFFFFFFu, bc, o);
        }
        if (lane == 0) {
            if (bs != 0.f) atomicAdd(&g_sum, (double)bs);
            if (bc) atomicAdd(&g_cnt, (unsigned int)bc);
        }
    }
}

// ------------------------------------------------------------------
__global__ void k_final(float* __restrict__ out) {
    double num_valid = 3.0 * (double)g_cnt;
    double denom = num_valid > 1.0 ? num_valid : 1.0;
    out[0] = (float)(8.0 * g_sum / denom);
}

// ------------------------------------------------------------------
extern "C" void kernel_launch(void* const* d_in, const int* in_sizes, int n_in,
                              void* d_out, int out_size) {
    const float* sdf   = (const float*)d_in[0];
    const float* rgb   = (const float*)d_in[1];
    const float* sem   = (const float*)d_in[2];
    const float* poses = (const float*)d_in[3];
    const float* views = (const float*)d_in[4];

    dim3 rb(32, 8);
    dim3 rg(SO / 32, SO / 8, SO);
    k_resize_pack<<<rg, rb>>>(sdf);
    dim3 mg(IMW / 32, IMH / 16, NVIEW);
    k_march<<<mg, 256>>>(poses);
    k_shade<<<(NPIX + 127) / 128, 128>>>(poses, rgb, sem, views);
    k_final<<<1, 1>>>((float*)d_out);
}